// round 5
// baseline (speedup 1.0000x reference)
#include <cuda_runtime.h>
#include <cuda_fp16.h>
#include <cstdint>

// ---------------- problem constants ----------------
#define IN_F   4096
#define OUT_F  4096
#define M_TOT  8192
#define BK     64           // fp16 k-slice: 128B rows (8 x 16B chunks)
#define KITERS (IN_F / BK)  // 64
#define BM     128
#define BN     128
#define NTH    128          // 4 warps, 64x64 warp tiles

// ---------------- static device scratch ----------------
// inverted transposed sign bits: bit=1 -> weight NEGATIVE; [kword][o]
__device__ uint32_t g_packT[(size_t)(IN_F / 32) * OUT_F];   // 2 MB
__device__ __half   g_xh[(size_t)M_TOT * IN_F];             // 64 MB, X in fp16
// per (kgroup, o): half2(s, s) as uint32
__device__ uint32_t g_ppT[(size_t)(IN_F / 128) * OUT_F];    // 512 KB

// ---------------- SMEM stage layout (bytes) ----------------
// A: 16384 (128 rows x 128B, xor-8 chunk swizzle)
// W: 1024  (2 kwords x 128 cols x 4B)
// S: 512   (128 cols x 4B half2 scale)
#define STG_STRIDE 17920
#define STG_A      0
#define STG_W      16384
#define STG_S      17408
#define STAGES     3
#define SM_TOTAL   (STAGES * STG_STRIDE)   // 53760

// ---------------- helpers ----------------
static __device__ __forceinline__ uint32_t smem_u32(const void* p) {
    uint32_t a;
    asm("{ .reg .u64 t; cvta.to.shared.u64 t, %1; cvt.u32.u64 %0, t; }"
        : "=r"(a) : "l"(p));
    return a;
}

#define CP_ASYNC16(dst, src) \
    asm volatile("cp.async.cg.shared.global [%0], [%1], 16;" :: "r"(dst), "l"(src))
#define CP_COMMIT()  asm volatile("cp.async.commit_group;" ::: "memory")
#define CP_WAIT1()   asm volatile("cp.async.wait_group 1;" ::: "memory")

static __device__ __forceinline__ void ldsm_x4(uint32_t* r, uint32_t addr) {
    asm volatile("ldmatrix.sync.aligned.m8n8.x4.shared.b16 {%0,%1,%2,%3}, [%4];"
                 : "=r"(r[0]), "=r"(r[1]), "=r"(r[2]), "=r"(r[3]) : "r"(addr));
}

static __device__ __forceinline__ void mma_fp16(float* d, const uint32_t* a,
                                                uint32_t b0, uint32_t b1) {
    asm volatile(
        "mma.sync.aligned.m16n8k16.row.col.f32.f16.f16.f32 "
        "{%0,%1,%2,%3}, {%4,%5,%6,%7}, {%8,%9}, {%0,%1,%2,%3};"
        : "+f"(d[0]), "+f"(d[1]), "+f"(d[2]), "+f"(d[3])
        : "r"(a[0]), "r"(a[1]), "r"(a[2]), "r"(a[3]), "r"(b0), "r"(b1));
}

// ============================================================
// Kernel 0: convert X fp32 -> fp16 (RN)
// ============================================================
__global__ void __launch_bounds__(256)
convert_x_kernel(const float4* __restrict__ x4) {
    size_t i = (size_t)blockIdx.x * 256 + threadIdx.x;   // 8 floats each
    float4 a = x4[2 * i];
    float4 b = x4[2 * i + 1];
    __half2 h0 = __floats2half2_rn(a.x, a.y);
    __half2 h1 = __floats2half2_rn(a.z, a.w);
    __half2 h2 = __floats2half2_rn(b.x, b.y);
    __half2 h3 = __floats2half2_rn(b.z, b.w);
    uint4 q;
    q.x = *reinterpret_cast<uint32_t*>(&h0);
    q.y = *reinterpret_cast<uint32_t*>(&h1);
    q.z = *reinterpret_cast<uint32_t*>(&h2);
    q.w = *reinterpret_cast<uint32_t*>(&h3);
    *reinterpret_cast<uint4*>(&g_xh[i * 8]) = q;
}

// ============================================================
// Kernel 1: pack INVERTED sign bits, transposed: packT[kw*4096 + o]
// bit b = 1 iff sign_weights[o, kw*32 + b] < 0  (i.e. flip sign)
// ============================================================
__global__ void __launch_bounds__(256)
pack_signs_kernel(const float* __restrict__ sw) {
    uint32_t W = blockIdx.x * 8u + (threadIdx.x >> 5);   // word 0..524287
    uint32_t lane = threadIdx.x & 31;
    uint32_t o = W >> 7;
    uint32_t kw = W & 127;
    float v = sw[(size_t)o * IN_F + kw * 32 + lane];
    uint32_t m = __ballot_sync(0xFFFFFFFFu, v < 0.0f);
    if (lane == 0) g_packT[(size_t)kw * OUT_F + o] = m;
}

// ============================================================
// Kernel 1b: transpose scales -> half2(s,s) words: ppT[kg*4096 + o]
// ============================================================
__global__ void __launch_bounds__(256)
pack_scales_kernel(const float* __restrict__ scales) {
    int idx = blockIdx.x * 256 + threadIdx.x;     // 131072 total
    int kg = idx >> 12;
    int o = idx & 4095;
    __half h = __float2half_rn(scales[(size_t)o * (IN_F / 128) + kg]);
    __half2 hh = __half2half2(h);
    g_ppT[(size_t)kg * OUT_F + o] = *reinterpret_cast<uint32_t*>(&hh);
}

// ============================================================
// Kernel 2: fp16 mma.sync GEMM, B built in registers from bitmask
// CTA 128x128xBK64, 4 warps 64x64.
// ============================================================
__global__ void __launch_bounds__(NTH, 2)
bitlinear_mma_kernel(float* __restrict__ out) {
    extern __shared__ char smem[];
    const uint32_t smem_base = smem_u32(smem);

    const int tid = threadIdx.x;
    const int wid = tid >> 5;
    const int lane = tid & 31;
    const int g = lane >> 2;
    const int t = lane & 3;
    const int wm_i = wid >> 1;
    const int wn_i = wid & 1;

    const int mt = blockIdx.x >> 5;
    const int nt = blockIdx.x & 31;
    const int m0 = mt * BM;
    const int o0 = nt * BN;

    // ---- A cp.async addressing ----
    const int ar = tid >> 3;
    const int ac = tid & 7;
    const __half* xsrc0 = g_xh + (size_t)(m0 + ar) * IN_F + ac * 8;
    const uint32_t adst_off0 = (uint32_t)(ar * 128 + ((ac ^ (ar & 7)) << 4));

    // ---- W/S cp.async addressing (thread subsets) ----
    const int wrow = tid >> 5;            // used when tid < 64
    const int wj = tid & 31;
    const int sj = tid - 64;              // used when 64 <= tid < 96

    float acc[4][8][4];
    #pragma unroll
    for (int mi = 0; mi < 4; ++mi)
        #pragma unroll
        for (int nj = 0; nj < 8; ++nj)
            #pragma unroll
            for (int r = 0; r < 4; ++r) acc[mi][nj][r] = 0.0f;

    // ---- ldmatrix A lane-address components ----
    const int a_row_l = wm_i * 64 + (lane & 15);
    const int a_hl = lane >> 4;

    // B column base for this lane: col_local = wn_i*64 + nj*8 + g
    const int colb = wn_i * 64 + g;
    const int t2 = 2 * t;

    // ---- stage fill lambda ----
    auto stage_fill = [&](int it, int s) {
        const uint32_t sb = smem_base + (uint32_t)(s * STG_STRIDE);
        const __half* src = xsrc0 + (size_t)it * BK;
        #pragma unroll
        for (int j = 0; j < 8; ++j)
            CP_ASYNC16(sb + adst_off0 + (uint32_t)(j * 2048),
                       (const char*)(src + (size_t)j * 16 * IN_F));
        if (tid < 64) {
            const uint32_t* wsrc = g_packT + (size_t)(2 * it + wrow) * OUT_F + o0 + wj * 4;
            CP_ASYNC16(sb + STG_W + (uint32_t)(wrow * 512 + wj * 16), (const char*)wsrc);
        } else if (tid < 96) {
            const uint32_t* ssrc = g_ppT + (size_t)(it >> 1) * OUT_F + o0 + sj * 4;
            CP_ASYNC16(sb + STG_S + (uint32_t)(sj * 16), (const char*)ssrc);
        }
    };

    // ---- prologue ----
    stage_fill(0, 0);
    CP_COMMIT();

    int sa = 0;

    #pragma unroll 1
    for (int it = 0; it < KITERS; ++it) {
        // prefetch next stage
        if (it < KITERS - 1) {
            const int sn3 = (sa == 2) ? 0 : sa + 1;
            stage_fill(it + 1, sn3);
        }
        CP_COMMIT();
        CP_WAIT1();
        __syncthreads();

        const char* st = smem + sa * STG_STRIDE;
        const uint32_t abase = smem_base + (uint32_t)(sa * STG_STRIDE);

        // ---- load sign words + scale words for this lane's 8 columns ----
        uint32_t w0[8], w1[8], pp[8];
        {
            const uint32_t* Wp = reinterpret_cast<const uint32_t*>(st + STG_W);
            const uint32_t* Sp = reinterpret_cast<const uint32_t*>(st + STG_S);
            #pragma unroll
            for (int nj = 0; nj < 8; ++nj) {
                const int c = colb + nj * 8;
                w0[nj] = Wp[c];
                w1[nj] = Wp[128 + c];
                pp[nj] = Sp[c];
            }
        }

        // ---- compute: 4 ksteps of k16 ----
        #pragma unroll
        for (int ks = 0; ks < 4; ++ks) {
            uint32_t af[4][4];
            #pragma unroll
            for (int mi = 0; mi < 4; ++mi) {
                const int r = a_row_l + mi * 16;
                const int ch = (2 * ks + a_hl) ^ (r & 7);
                ldsm_x4(af[mi], abase + (uint32_t)(r * 128 + (ch << 4)));
            }
            #pragma unroll
            for (int nj = 0; nj < 8; ++nj) {
                // select word + shift for this kstep: bits {0,1,8,9} of v
                uint32_t wv = (ks & 2) ? w1[nj] : w0[nj];
                uint32_t v = wv >> (t2 + ((ks & 1) << 4));
                uint32_t b0 = pp[nj] ^ (((v << 15) & 0x8000u) | ((v << 30) & 0x80000000u));
                uint32_t b1 = pp[nj] ^ (((v << 7) & 0x8000u) | ((v << 22) & 0x80000000u));
                #pragma unroll
                for (int mi = 0; mi < 4; ++mi)
                    mma_fp16(acc[mi][nj], af[mi], b0, b1);
            }
        }

        sa = (sa == 2) ? 0 : sa + 1;
    }

    // ---- epilogue: direct STG.64 ----
    #pragma unroll
    for (int mi = 0; mi < 4; ++mi) {
        const int row = m0 + wm_i * 64 + mi * 16 + g;
        #pragma unroll
        for (int nj = 0; nj < 8; ++nj) {
            const int col = o0 + wn_i * 64 + nj * 8 + 2 * t;
            float2 v0 = make_float2(acc[mi][nj][0], acc[mi][nj][1]);
            float2 v1 = make_float2(acc[mi][nj][2], acc[mi][nj][3]);
            *reinterpret_cast<float2*>(out + (size_t)row * OUT_F + col) = v0;
            *reinterpret_cast<float2*>(out + (size_t)(row + 8) * OUT_F + col) = v1;
        }
    }
}

// ============================================================
// launch
// ============================================================
extern "C" void kernel_launch(void* const* d_in, const int* in_sizes, int n_in,
                              void* d_out, int out_size) {
    const float* x      = (const float*)d_in[0];
    const float* sw     = (const float*)d_in[1];
    const float* scales = (const float*)d_in[2];
    float* out = (float*)d_out;

    cudaFuncSetAttribute(bitlinear_mma_kernel,
                         cudaFuncAttributeMaxDynamicSharedMemorySize, SM_TOTAL);

    // 0) X -> fp16
    convert_x_kernel<<<(M_TOT * (size_t)IN_F) / (8 * 256), 256>>>((const float4*)x);

    // 1) pack inverted signs (transposed) + scale half2 table
    pack_signs_kernel<<<65536, 256>>>(sw);
    pack_scales_kernel<<<512, 256>>>(scales);

    // 2) GEMM: 64 M-tiles x 32 N-tiles
    bitlinear_mma_kernel<<<(M_TOT / BM) * (OUT_F / BN), NTH, SM_TOTAL>>>(out);
}

// round 6
// speedup vs baseline: 1.0587x; 1.0587x over previous
#include <cuda_runtime.h>
#include <cuda_fp16.h>
#include <cstdint>

// ---------------- problem constants ----------------
#define IN_F   4096
#define OUT_F  4096
#define M_TOT  8192
#define BK     128          // k per iteration (= one scale group, 256B rows)
#define KITERS (IN_F / BK)  // 32
#define BM     128
#define BN     128
#define NTH    128          // 4 warps, 64x64 warp tiles

// ---------------- static device scratch ----------------
// inverted transposed sign bits: bit=1 -> weight NEGATIVE; [kword][o]
__device__ uint32_t g_packT[(size_t)(IN_F / 32) * OUT_F];   // 2 MB
__device__ __half   g_xh[(size_t)M_TOT * IN_F];             // 64 MB
// per (kgroup, o): half2(s, s) as uint32
__device__ uint32_t g_ppT[(size_t)(IN_F / 128) * OUT_F];    // 512 KB

// ---------------- SMEM stage layout (bytes) ----------------
// A: 32768 (128 rows x 256B, 16 chunks, xor-8 swizzle)
// W: 2048  (4 kwords x 128 cols x 4B)
// S: 512   (128 cols x 4B half2 scale)
#define STG_A      0
#define STG_W      32768
#define STG_S      34816
#define STG_STRIDE 35328
#define STAGES     3
#define SM_TOTAL   (STAGES * STG_STRIDE)   // 105984

// ---------------- helpers ----------------
static __device__ __forceinline__ uint32_t smem_u32(const void* p) {
    uint32_t a;
    asm("{ .reg .u64 t; cvta.to.shared.u64 t, %1; cvt.u32.u64 %0, t; }"
        : "=r"(a) : "l"(p));
    return a;
}

#define CP_ASYNC16(dst, src) \
    asm volatile("cp.async.cg.shared.global [%0], [%1], 16;" :: "r"(dst), "l"(src))
#define CP_COMMIT()  asm volatile("cp.async.commit_group;" ::: "memory")
#define CP_WAIT1()   asm volatile("cp.async.wait_group 1;" ::: "memory")

static __device__ __forceinline__ void ldsm_x4(uint32_t* r, uint32_t addr) {
    asm volatile("ldmatrix.sync.aligned.m8n8.x4.shared.b16 {%0,%1,%2,%3}, [%4];"
                 : "=r"(r[0]), "=r"(r[1]), "=r"(r[2]), "=r"(r[3]) : "r"(addr));
}

static __device__ __forceinline__ void mma_fp16(float* d, const uint32_t* a,
                                                uint32_t b0, uint32_t b1) {
    asm volatile(
        "mma.sync.aligned.m16n8k16.row.col.f32.f16.f16.f32 "
        "{%0,%1,%2,%3}, {%4,%5,%6,%7}, {%8,%9}, {%0,%1,%2,%3};"
        : "+f"(d[0]), "+f"(d[1]), "+f"(d[2]), "+f"(d[3])
        : "r"(a[0]), "r"(a[1]), "r"(a[2]), "r"(a[3]), "r"(b0), "r"(b1));
}

// ============================================================
// Kernel 0: convert X fp32 -> fp16 (RN)
// ============================================================
__global__ void __launch_bounds__(256)
convert_x_kernel(const float4* __restrict__ x4) {
    size_t i = (size_t)blockIdx.x * 256 + threadIdx.x;
    float4 a = x4[2 * i];
    float4 b = x4[2 * i + 1];
    __half2 h0 = __floats2half2_rn(a.x, a.y);
    __half2 h1 = __floats2half2_rn(a.z, a.w);
    __half2 h2 = __floats2half2_rn(b.x, b.y);
    __half2 h3 = __floats2half2_rn(b.z, b.w);
    uint4 q;
    q.x = *reinterpret_cast<uint32_t*>(&h0);
    q.y = *reinterpret_cast<uint32_t*>(&h1);
    q.z = *reinterpret_cast<uint32_t*>(&h2);
    q.w = *reinterpret_cast<uint32_t*>(&h3);
    *reinterpret_cast<uint4*>(&g_xh[i * 8]) = q;
}

// ============================================================
// Kernel 1: pack INVERTED sign bits, transposed: packT[kw*4096 + o]
// ============================================================
__global__ void __launch_bounds__(256)
pack_signs_kernel(const float* __restrict__ sw) {
    uint32_t W = blockIdx.x * 8u + (threadIdx.x >> 5);
    uint32_t lane = threadIdx.x & 31;
    uint32_t o = W >> 7;
    uint32_t kw = W & 127;
    float v = sw[(size_t)o * IN_F + kw * 32 + lane];
    uint32_t m = __ballot_sync(0xFFFFFFFFu, v < 0.0f);
    if (lane == 0) g_packT[(size_t)kw * OUT_F + o] = m;
}

// ============================================================
// Kernel 1b: scales -> half2(s,s) words, transposed: ppT[kg*4096 + o]
// ============================================================
__global__ void __launch_bounds__(256)
pack_scales_kernel(const float* __restrict__ scales) {
    int idx = blockIdx.x * 256 + threadIdx.x;
    int kg = idx >> 12;
    int o = idx & 4095;
    __half h = __float2half_rn(scales[(size_t)o * (IN_F / 128) + kg]);
    __half2 hh = __half2half2(h);
    g_ppT[(size_t)kg * OUT_F + o] = *reinterpret_cast<uint32_t*>(&hh);
}

// ============================================================
// Kernel 2: fp16 mma.sync GEMM, BK=128, B built in registers
// ============================================================
__global__ void __launch_bounds__(NTH, 2)
bitlinear_mma_kernel(float* __restrict__ out) {
    extern __shared__ char smem[];
    const uint32_t smem_base = smem_u32(smem);

    const int tid = threadIdx.x;
    const int wid = tid >> 5;
    const int lane = tid & 31;
    const int g = lane >> 2;
    const int t = lane & 3;
    const int wm_i = wid >> 1;
    const int wn_i = wid & 1;

    const int mt = blockIdx.x >> 5;
    const int nt = blockIdx.x & 31;
    const int m0 = mt * BM;
    const int o0 = nt * BN;

    // ---- A cp.async addressing: 2048 chunks, 16 per thread ----
    const int arow = tid >> 4;           // base row 0..7, rows arow + 8j
    const int ac = tid & 15;             // chunk 0..15
    const __half* xsrc0 = g_xh + (size_t)(m0 + arow) * IN_F + ac * 8;
    const uint32_t adst0 = (uint32_t)(arow * 256 + ((ac ^ (arow & 7)) << 4));

    // ---- W/S cp.async addressing ----
    const int wkw = tid >> 5;            // kword 0..3
    const int wcg = tid & 31;            // col group

    float acc[4][8][4];
    #pragma unroll
    for (int mi = 0; mi < 4; ++mi)
        #pragma unroll
        for (int nj = 0; nj < 8; ++nj)
            #pragma unroll
            for (int r = 0; r < 4; ++r) acc[mi][nj][r] = 0.0f;

    // ---- ldmatrix A lane components ----
    const int a_row_l = wm_i * 64 + (lane & 15);
    const int a_hl = lane >> 4;          // 0/1 -> chunk 2ks + hl

    const int colb = wn_i * 64 + g;      // B col base
    const int t2 = 2 * t;

    auto stage_fill = [&](int it, int s) {
        const uint32_t sb = smem_base + (uint32_t)(s * STG_STRIDE);
        const __half* src = xsrc0 + (size_t)it * BK;
        #pragma unroll
        for (int j = 0; j < 16; ++j)
            CP_ASYNC16(sb + adst0 + (uint32_t)(j * 2048),
                       (const char*)(src + (size_t)j * 8 * IN_F));
        // W: 4 kwords x 128 cols, one 16B chunk per thread
        {
            const uint32_t* wsrc = g_packT + (size_t)(4 * it + wkw) * OUT_F + o0 + wcg * 4;
            CP_ASYNC16(sb + STG_W + (uint32_t)(tid * 16), (const char*)wsrc);
        }
        // S: 128 cols, threads 0..31
        if (tid < 32) {
            const uint32_t* ssrc = g_ppT + (size_t)it * OUT_F + o0 + tid * 4;
            CP_ASYNC16(sb + STG_S + (uint32_t)(tid * 16), (const char*)ssrc);
        }
    };

    stage_fill(0, 0);
    CP_COMMIT();

    int sa = 0;

    #pragma unroll 1
    for (int it = 0; it < KITERS; ++it) {
        if (it < KITERS - 1) {
            const int sn3 = (sa == 2) ? 0 : sa + 1;
            stage_fill(it + 1, sn3);
        }
        CP_COMMIT();
        CP_WAIT1();
        __syncthreads();

        const char* st = smem + sa * STG_STRIDE;
        const uint32_t abase = smem_base + (uint32_t)(sa * STG_STRIDE);

        // ---- sign words (4 kwords) + scale word for this lane's 8 cols ----
        uint32_t w[4][8], pp[8];
        {
            const uint32_t* Wp = reinterpret_cast<const uint32_t*>(st + STG_W);
            const uint32_t* Sp = reinterpret_cast<const uint32_t*>(st + STG_S);
            #pragma unroll
            for (int nj = 0; nj < 8; ++nj) {
                const int c = colb + nj * 8;
                w[0][nj] = Wp[c];
                w[1][nj] = Wp[128 + c];
                w[2][nj] = Wp[256 + c];
                w[3][nj] = Wp[384 + c];
                pp[nj] = Sp[c];
            }
        }

        // ---- software-pipelined A fragments across 8 ksteps ----
        uint32_t af[2][4][4];
        #pragma unroll
        for (int mi = 0; mi < 4; ++mi) {
            const int r = a_row_l + mi * 16;
            const int ch = a_hl ^ (r & 7);              // ks=0
            ldsm_x4(af[0][mi], abase + (uint32_t)(r * 256 + (ch << 4)));
        }

        #pragma unroll
        for (int ks = 0; ks < 8; ++ks) {
            const int cur = ks & 1;
            if (ks < 7) {
                #pragma unroll
                for (int mi = 0; mi < 4; ++mi) {
                    const int r = a_row_l + mi * 16;
                    const int ch = (2 * (ks + 1) + a_hl) ^ (r & 7);
                    ldsm_x4(af[cur ^ 1][mi], abase + (uint32_t)(r * 256 + (ch << 4)));
                }
            }
            const int kw = ks >> 1;
            const int sh = t2 + ((ks & 1) << 4);
            #pragma unroll
            for (int nj = 0; nj < 8; ++nj) {
                uint32_t v = w[kw][nj] >> sh;
                uint32_t b0 = pp[nj] ^ (((v << 15) & 0x8000u) | ((v << 30) & 0x80000000u));
                uint32_t b1 = pp[nj] ^ (((v << 7) & 0x8000u) | ((v << 22) & 0x80000000u));
                #pragma unroll
                for (int mi = 0; mi < 4; ++mi)
                    mma_fp16(acc[mi][nj], af[cur][mi], b0, b1);
            }
        }

        sa = (sa == 2) ? 0 : sa + 1;
    }

    // ---- epilogue: direct STG.64 ----
    #pragma unroll
    for (int mi = 0; mi < 4; ++mi) {
        const int row = m0 + wm_i * 64 + mi * 16 + g;
        #pragma unroll
        for (int nj = 0; nj < 8; ++nj) {
            const int col = o0 + wn_i * 64 + nj * 8 + 2 * t;
            float2 v0 = make_float2(acc[mi][nj][0], acc[mi][nj][1]);
            float2 v1 = make_float2(acc[mi][nj][2], acc[mi][nj][3]);
            *reinterpret_cast<float2*>(out + (size_t)row * OUT_F + col) = v0;
            *reinterpret_cast<float2*>(out + (size_t)(row + 8) * OUT_F + col) = v1;
        }
    }
}

// ============================================================
// launch
// ============================================================
extern "C" void kernel_launch(void* const* d_in, const int* in_sizes, int n_in,
                              void* d_out, int out_size) {
    const float* x      = (const float*)d_in[0];
    const float* sw     = (const float*)d_in[1];
    const float* scales = (const float*)d_in[2];
    float* out = (float*)d_out;

    cudaFuncSetAttribute(bitlinear_mma_kernel,
                         cudaFuncAttributeMaxDynamicSharedMemorySize, SM_TOTAL);

    convert_x_kernel<<<(M_TOT * (size_t)IN_F) / (8 * 256), 256>>>((const float4*)x);
    pack_signs_kernel<<<65536, 256>>>(sw);
    pack_scales_kernel<<<512, 256>>>(scales);

    bitlinear_mma_kernel<<<(M_TOT / BM) * (OUT_F / BN), NTH, SM_TOTAL>>>(out);
}